// round 12
// baseline (speedup 1.0000x reference)
#include <cuda_runtime.h>
#include <cstdint>

// ---------------- problem constants ----------------
#define S_ROWS 16384
#define K_DIM  1024
#define D_TOT  6400
#define BINS   20

// ---------------- quantization scales ----------------
#define QS1 (6.0f / 127.0f)          // level-1 scale
#define QS2 (QS1 / 254.0f)           // level-2 scale (covers residual range)
#define QI1 (127.0f / 6.0f)
#define QI2 (QI1 * 254.0f)

// ---------------- tiling ----------------
#define BM 128
#define BN 128
#define BKB 128                      // K bytes (=elems, int8) per stage
#define STAGES 3
#define KT (K_DIM / BKB)             // 8
#define NTHREADS 512                 // 16 warps: 4(M) x 4(N), warp tile 32x32

#define PLANE 16384                  // 128 rows x 128 B
#define STAGE_B (4 * PLANE)          // Aq1, Aq2, Bq1, Bq2 = 64KB
#define OFF_META (STAGES * STAGE_B)            // 196608
#define SMEM_TOTAL (OFF_META + 3 * BN * 4)     // 198144

// ---------------- global scratch ----------------
__device__ int8_t g_xq1[S_ROWS * K_DIM];
__device__ int8_t g_xq2[S_ROWS * K_DIM];
__device__ int8_t g_wq1[D_TOT * K_DIM];
__device__ int8_t g_wq2[D_TOT * K_DIM];
__device__ float g_hist[D_TOT * BINS];

// ---------------- helpers ----------------
__device__ __forceinline__ uint32_t smem_u32(const void* p) {
    uint32_t a;
    asm("{ .reg .u64 t; cvta.to.shared.u64 t, %1; cvt.u32.u64 %0, t; }"
        : "=r"(a) : "l"(p));
    return a;
}
__device__ __forceinline__ uint32_t sw128(uint32_t off) {
    return off ^ ((off >> 3) & 0x70);
}
__device__ __forceinline__ void cp16(uint32_t s, const void* g) {
    asm volatile("cp.async.cg.shared.global [%0], [%1], 16;" :: "r"(s), "l"(g));
}
#define CP_COMMIT() asm volatile("cp.async.commit_group;" ::: "memory")
#define CP_WAIT(n)  asm volatile("cp.async.wait_group %0;" :: "n"(n) : "memory")

__device__ __forceinline__ void ldsm4(uint32_t* r, uint32_t addr) {
    asm volatile("ldmatrix.sync.aligned.m8n8.x4.shared.b16 {%0,%1,%2,%3}, [%4];"
        : "=r"(r[0]), "=r"(r[1]), "=r"(r[2]), "=r"(r[3]) : "r"(addr));
}
__device__ __forceinline__ void mma_s8(int* d, const uint32_t* a,
                                       uint32_t b0, uint32_t b1) {
    asm volatile(
        "mma.sync.aligned.m16n8k32.row.col.s32.s8.s8.s32 "
        "{%0,%1,%2,%3}, {%4,%5,%6,%7}, {%8,%9}, {%0,%1,%2,%3};"
        : "+r"(d[0]), "+r"(d[1]), "+r"(d[2]), "+r"(d[3])
        : "r"(a[0]), "r"(a[1]), "r"(a[2]), "r"(a[3]), "r"(b0), "r"(b1));
}

// ---------------- quantize: fp32 -> two-level int8 ----------------
__global__ void quant_kernel(const float4* __restrict__ src,
                             char4* __restrict__ q1o, char4* __restrict__ q2o, int n4)
{
    int i = blockIdx.x * blockDim.x + threadIdx.x;
    if (i >= n4) return;
    float4 v = src[i];
    float a[4] = {v.x, v.y, v.z, v.w};
    int q1[4], q2[4];
    #pragma unroll
    for (int k = 0; k < 4; ++k) {
        int t = __float2int_rn(a[k] * QI1);
        t = max(-127, min(127, t));
        float r = a[k] - (float)t * QS1;
        int u = __float2int_rn(r * QI2);
        u = max(-127, min(127, u));
        q1[k] = t; q2[k] = u;
    }
    q1o[i] = make_char4((char)q1[0], (char)q1[1], (char)q1[2], (char)q1[3]);
    q2o[i] = make_char4((char)q2[0], (char)q2[1], (char)q2[2], (char)q2[3]);
}

__global__ void zero_hist_kernel() {
    int i = blockIdx.x * blockDim.x + threadIdx.x;
    if (i < D_TOT * BINS) g_hist[i] = 0.0f;
}

// ---------------- fused GEMM + histogram ----------------
__global__ __launch_bounds__(NTHREADS, 1)
void gemm_hist_kernel(const float* __restrict__ mins, const float* __restrict__ maxs)
{
    extern __shared__ char smem[];
    const uint32_t sb = smem_u32(smem);
    const int tid  = threadIdx.x;
    const int wid  = tid >> 5;
    const int lane = tid & 31;
    const int wm = wid & 3;          // warp M index (0..3) -> rows wm*32
    const int wn = wid >> 2;         // warp N index (0..3) -> cols wn*32

    const int m0  = blockIdx.y * BM;
    const int n0t = blockIdx.x * BN;

    const int8_t* A1 = g_xq1 + (size_t)m0 * K_DIM;
    const int8_t* A2 = g_xq2 + (size_t)m0 * K_DIM;
    const int8_t* B1 = g_wq1 + (size_t)n0t * K_DIM;
    const int8_t* B2 = g_wq2 + (size_t)n0t * K_DIM;

    float* mnS = (float*)(smem + OFF_META);
    float* mxS = mnS + BN;
    float* scS = mxS + BN;
    if (tid < BN) {
        float mn = mins[n0t + tid], mx = maxs[n0t + tid];
        mnS[tid] = mn; mxS[tid] = mx;
        scS[tid] = (float)BINS / (mx - mn);
    }

    // loader: 512 threads, 128 rows x 128B per plane -> 2 rows/thread/plane
    const int lrow = tid >> 3;       // 0..63
    const int lcol = tid & 7;        // 16B chunk

    auto load_stage = [&](int kt) {
        const uint32_t st = sb + (uint32_t)((kt % STAGES) * STAGE_B);
        #pragma unroll
        for (int i = 0; i < 2; ++i) {
            int row = lrow + 64 * i;
            uint32_t soff = sw128((uint32_t)(row * 128 + lcol * 16));
            size_t go = (size_t)row * K_DIM + (size_t)kt * BKB + lcol * 16;
            cp16(st + 0 * PLANE + soff, A1 + go);
            cp16(st + 1 * PLANE + soff, A2 + go);
            cp16(st + 2 * PLANE + soff, B1 + go);
            cp16(st + 3 * PLANE + soff, B2 + go);
        }
    };

    int accA[2][4][4], accB[2][4][4];
    #pragma unroll
    for (int i = 0; i < 2; ++i)
        #pragma unroll
        for (int j = 0; j < 4; ++j)
            #pragma unroll
            for (int r = 0; r < 4; ++r) { accA[i][j][r] = 0; accB[i][j][r] = 0; }

    load_stage(0); CP_COMMIT();
    load_stage(1); CP_COMMIT();

    // A ldmatrix addressing (16x32 int8 tile as 4 8x8-b16 matrices)
    const int arow_l = lane & 15;
    const int akoff  = (lane >> 4) << 4;     // 0 or 16
    // B ldmatrix addressing (two 8x32 n-tiles per x4)
    const int brow_l = (lane & 7) + ((lane >> 4) << 3);
    const int bkoff  = ((lane >> 3) & 1) << 4;

    for (int kt = 0; kt < KT; ++kt) {
        if (kt < KT - 1) { CP_WAIT(1); } else { CP_WAIT(0); }
        __syncthreads();
        if (kt + 2 < KT) { load_stage(kt + 2); CP_COMMIT(); }

        const uint32_t st = sb + (uint32_t)((kt % STAGES) * STAGE_B);
        #pragma unroll
        for (int ks = 0; ks < BKB / 32; ++ks) {
            uint32_t a1[2][4], a2[2][4];
            #pragma unroll
            for (int mf = 0; mf < 2; ++mf) {
                int arow = wm * 32 + mf * 16 + arow_l;
                uint32_t off = (uint32_t)(arow * 128 + ks * 32) + akoff;
                ldsm4(a1[mf], st + 0 * PLANE + sw128(off));
                ldsm4(a2[mf], st + 1 * PLANE + sw128(off));
            }
            uint32_t b1[2][4], b2[2][4];
            #pragma unroll
            for (int ng = 0; ng < 2; ++ng) {
                int nrow = wn * 32 + ng * 16 + brow_l;
                uint32_t off = (uint32_t)(nrow * 128 + ks * 32) + bkoff;
                ldsm4(b1[ng], st + 2 * PLANE + sw128(off));
                ldsm4(b2[ng], st + 3 * PLANE + sw128(off));
            }
            #pragma unroll
            for (int mf = 0; mf < 2; ++mf)
                #pragma unroll
                for (int nf = 0; nf < 4; ++nf) {
                    int ng = nf >> 1, h = (nf & 1) * 2;
                    mma_s8(accA[mf][nf], a1[mf], b1[ng][h], b1[ng][h + 1]);
                    mma_s8(accB[mf][nf], a1[mf], b2[ng][h], b2[ng][h + 1]);
                    mma_s8(accB[mf][nf], a2[mf], b1[ng][h], b1[ng][h + 1]);
                }
        }
    }
    __syncthreads();

    // ---------------- histogram epilogue ----------------
    // 16 warp-private hists of 32 cols x 20 bins
    float* hall = (float*)smem;                 // 16 x 32 x 20 = 40KB
    for (int i = tid; i < 16 * 32 * BINS; i += NTHREADS) hall[i] = 0.0f;
    __syncthreads();

    const float S11 = QS1 * QS1;
    const float S12 = QS1 * QS2;

    float* hw = hall + wid * (32 * BINS);
    const int q = lane & 3;
    #pragma unroll
    for (int nf = 0; nf < 4; ++nf) {
        #pragma unroll
        for (int half = 0; half < 2; ++half) {
            int lc = nf * 8 + 2 * q + half;      // col within warp's 32
            int c  = wn * 32 + lc;
            float mn = mnS[c], mx = mxS[c], sc = scS[c];
            #pragma unroll
            for (int mf = 0; mf < 2; ++mf)
                #pragma unroll
                for (int rp = 0; rp < 2; ++rp) {
                    float p = S11 * (float)accA[mf][nf][2 * rp + half]
                            + S12 * (float)accB[mf][nf][2 * rp + half];
                    if (p >= mn && p <= mx) {
                        int b = min((int)((p - mn) * sc), BINS - 1);
                        atomicAdd(&hw[lc * BINS + b], 1.0f);
                    }
                }
        }
    }
    __syncthreads();

    // merge 4 warp copies per column group -> global atomics
    for (int i = tid; i < BN * BINS; i += NTHREADS) {
        int c = i / BINS, b = i - c * BINS;
        int cwn = c >> 5, lc = c & 31;
        float s = 0.0f;
        #pragma unroll
        for (int k = 0; k < 4; ++k)
            s += hall[(cwn * 4 + k) * (32 * BINS) + lc * BINS + b];
        if (s != 0.0f)
            atomicAdd(&g_hist[(size_t)n0t * BINS + i], s);
    }
}

// ---------------- normalize ----------------
__global__ void normalize_kernel(float* __restrict__ out)
{
    int row  = blockIdx.x * 4 + (threadIdx.x >> 5);
    int lane = threadIdx.x & 31;
    if (row >= D_TOT) return;
    float v = (lane < BINS) ? g_hist[row * BINS + lane] : 0.0f;
    float s = v * v;
    #pragma unroll
    for (int o = 16; o; o >>= 1) s += __shfl_xor_sync(0xFFFFFFFFu, s, o);
    float denom = fmaxf(sqrtf(s), 1e-12f);
    if (lane < BINS) out[row * BINS + lane] = v / denom;
}

extern "C" void kernel_launch(void* const* d_in, const int* in_sizes, int n_in,
                              void* d_out, int out_size)
{
    const float* x    = (const float*)d_in[0];
    const float* W    = (const float*)d_in[1];
    const float* mins = (const float*)d_in[2];
    const float* maxs = (const float*)d_in[3];
    float* out = (float*)d_out;

    static int attr_set = 0;
    if (!attr_set) {
        cudaFuncSetAttribute(gemm_hist_kernel,
                             cudaFuncAttributeMaxDynamicSharedMemorySize, SMEM_TOTAL);
        attr_set = 1;
    }

    int8_t *xq1, *xq2, *wq1, *wq2;
    cudaGetSymbolAddress((void**)&xq1, g_xq1);
    cudaGetSymbolAddress((void**)&xq2, g_xq2);
    cudaGetSymbolAddress((void**)&wq1, g_wq1);
    cudaGetSymbolAddress((void**)&wq2, g_wq2);

    int nx4 = S_ROWS * K_DIM / 4;
    int nw4 = D_TOT * K_DIM / 4;
    quant_kernel<<<(nx4 + 255) / 256, 256>>>((const float4*)x, (char4*)xq1, (char4*)xq2, nx4);
    quant_kernel<<<(nw4 + 255) / 256, 256>>>((const float4*)W, (char4*)wq1, (char4*)wq2, nw4);
    zero_hist_kernel<<<(D_TOT * BINS + 255) / 256, 256>>>();

    dim3 grid(D_TOT / BN, S_ROWS / BM);   // (50, 128)
    gemm_hist_kernel<<<grid, NTHREADS, SMEM_TOTAL>>>(mins, maxs);

    normalize_kernel<<<(D_TOT + 3) / 4, 128>>>(out);
}

// round 14
// speedup vs baseline: 2.4097x; 2.4097x over previous
#include <cuda_runtime.h>
#include <cuda_bf16.h>
#include <cstdint>

// ---------------- problem constants ----------------
#define S_ROWS 16384
#define K_DIM  1024
#define D_TOT  6400
#define BINS   20

// ---------------- tiling ----------------
#define BM 256
#define BN 128
#define BK 64
#define KT (K_DIM / BK)          // 16
#define NTHREADS 512             // 16 warps: 4(M) x 4(N), warp tile 64x32

#define PLANE_A 32768            // 256 rows x 128B
#define PLANE_B_SZ 16384         // 128 rows x 128B
#define OFF_BH (2 * PLANE_A)                 // 65536
#define OFF_BL (OFF_BH + PLANE_B_SZ)         // 81920
#define STAGE_B (OFF_BL + PLANE_B_SZ)        // 98304 (96KB)
#define OFF_META (2 * STAGE_B)               // 196608
#define SMEM_TOTAL (OFF_META + 3 * BN * 4)   // 198144

// ---------------- global scratch ----------------
__device__ __nv_bfloat16 g_xhi[S_ROWS * K_DIM];
__device__ __nv_bfloat16 g_xlo[S_ROWS * K_DIM];
__device__ __nv_bfloat16 g_whi[D_TOT * K_DIM];
__device__ __nv_bfloat16 g_wlo[D_TOT * K_DIM];
__device__ float g_hist[D_TOT * BINS];

// ---------------- helpers ----------------
__device__ __forceinline__ uint32_t smem_u32(const void* p) {
    uint32_t a;
    asm("{ .reg .u64 t; cvta.to.shared.u64 t, %1; cvt.u32.u64 %0, t; }"
        : "=r"(a) : "l"(p));
    return a;
}
__device__ __forceinline__ uint32_t sw128(uint32_t off) {
    return off ^ ((off >> 3) & 0x70);
}
__device__ __forceinline__ void cp16(uint32_t s, const void* g) {
    asm volatile("cp.async.cg.shared.global [%0], [%1], 16;" :: "r"(s), "l"(g));
}
#define CP_COMMIT() asm volatile("cp.async.commit_group;" ::: "memory")
#define CP_WAIT(n)  asm volatile("cp.async.wait_group %0;" :: "n"(n) : "memory")

__device__ __forceinline__ void ldsm4(uint32_t* r, uint32_t addr) {
    asm volatile("ldmatrix.sync.aligned.m8n8.x4.shared.b16 {%0,%1,%2,%3}, [%4];"
        : "=r"(r[0]), "=r"(r[1]), "=r"(r[2]), "=r"(r[3]) : "r"(addr));
}
__device__ __forceinline__ void mma_bf16(float* d, const uint32_t* a,
                                         uint32_t b0, uint32_t b1) {
    asm volatile(
        "mma.sync.aligned.m16n8k16.row.col.f32.bf16.bf16.f32 "
        "{%0,%1,%2,%3}, {%4,%5,%6,%7}, {%8,%9}, {%0,%1,%2,%3};"
        : "+f"(d[0]), "+f"(d[1]), "+f"(d[2]), "+f"(d[3])
        : "r"(a[0]), "r"(a[1]), "r"(a[2]), "r"(a[3]), "r"(b0), "r"(b1));
}

// ---------------- pre-split: fp32 -> bf16 hi/lo planes ----------------
__global__ void split_kernel(const float4* __restrict__ src,
                             uint2* __restrict__ hi, uint2* __restrict__ lo, int n4)
{
    int i = blockIdx.x * blockDim.x + threadIdx.x;
    if (i >= n4) return;
    float4 v = src[i];
    uint32_t h0, h1, g0, g1;
    asm("cvt.rn.bf16x2.f32 %0, %1, %2;" : "=r"(h0) : "f"(v.y), "f"(v.x));
    asm("cvt.rn.bf16x2.f32 %0, %1, %2;" : "=r"(h1) : "f"(v.w), "f"(v.z));
    float l0 = v.x - __uint_as_float(h0 << 16);
    float l1 = v.y - __uint_as_float(h0 & 0xFFFF0000u);
    float l2 = v.z - __uint_as_float(h1 << 16);
    float l3 = v.w - __uint_as_float(h1 & 0xFFFF0000u);
    asm("cvt.rn.bf16x2.f32 %0, %1, %2;" : "=r"(g0) : "f"(l1), "f"(l0));
    asm("cvt.rn.bf16x2.f32 %0, %1, %2;" : "=r"(g1) : "f"(l3), "f"(l2));
    hi[i] = make_uint2(h0, h1);
    lo[i] = make_uint2(g0, g1);
}

__global__ void zero_hist_kernel() {
    int i = blockIdx.x * blockDim.x + threadIdx.x;
    if (i < D_TOT * BINS) g_hist[i] = 0.0f;
}

// ---------------- fused GEMM + histogram ----------------
__global__ __launch_bounds__(NTHREADS, 1)
void gemm_hist_kernel(const float* __restrict__ mins, const float* __restrict__ maxs)
{
    extern __shared__ char smem[];
    const uint32_t sb = smem_u32(smem);
    const int tid  = threadIdx.x;
    const int wid  = tid >> 5;
    const int lane = tid & 31;
    const int wm = wid & 3;          // warp M index (0..3) -> rows wm*64
    const int wn = wid >> 2;         // warp N index (0..3) -> cols wn*32

    const int m0  = blockIdx.y * BM;
    const int n0t = blockIdx.x * BN;

    const __nv_bfloat16* Ah = g_xhi + (size_t)m0 * K_DIM;
    const __nv_bfloat16* Al = g_xlo + (size_t)m0 * K_DIM;
    const __nv_bfloat16* Bh = g_whi + (size_t)n0t * K_DIM;
    const __nv_bfloat16* Bl = g_wlo + (size_t)n0t * K_DIM;

    float* mnS = (float*)(smem + OFF_META);
    float* mxS = mnS + BN;
    float* scS = mxS + BN;
    if (tid < BN) {
        float mn = mins[n0t + tid], mx = maxs[n0t + tid];
        mnS[tid] = mn; mxS[tid] = mx;
        scS[tid] = (float)BINS / (mx - mn);
    }

    // loader: 512 threads; 128B rows as 8 x 16B chunks
    const int lrow = tid >> 3;       // 0..63
    const int lcol = tid & 7;

    auto load_stage = [&](int kt) {
        const uint32_t st = sb + (uint32_t)((kt & 1) * STAGE_B);
        const size_t kb = (size_t)kt * BK + lcol * 8;
        #pragma unroll
        for (int i = 0; i < 4; ++i) {            // A: 256 rows
            int row = lrow + 64 * i;
            uint32_t soff = sw128((uint32_t)(row * 128 + lcol * 16));
            size_t go = (size_t)row * K_DIM + kb;
            cp16(st + soff, Ah + go);
            cp16(st + PLANE_A + soff, Al + go);
        }
        #pragma unroll
        for (int i = 0; i < 2; ++i) {            // B: 128 rows
            int row = lrow + 64 * i;
            uint32_t soff = sw128((uint32_t)(row * 128 + lcol * 16));
            size_t go = (size_t)row * K_DIM + kb;
            cp16(st + OFF_BH + soff, Bh + go);
            cp16(st + OFF_BL + soff, Bl + go);
        }
    };

    float acc[4][4][4];
    #pragma unroll
    for (int i = 0; i < 4; ++i)
        #pragma unroll
        for (int j = 0; j < 4; ++j)
            #pragma unroll
            for (int r = 0; r < 4; ++r) acc[i][j][r] = 0.0f;

    load_stage(0); CP_COMMIT();

    const int l15   = lane & 15;
    const int khalf = (lane >> 4) << 4;   // k-half byte offset (0 or 16)

    for (int kt = 0; kt < KT; ++kt) {
        CP_WAIT(0);
        __syncthreads();                  // stage kt resident; prev stage consumed
        if (kt + 1 < KT) { load_stage(kt + 1); CP_COMMIT(); }

        const uint32_t st = sb + (uint32_t)((kt & 1) * STAGE_B);
        #pragma unroll
        for (int ks = 0; ks < BK / 16; ++ks) {
            // B fragments for this warp's 32 cols (2 n16 groups x 2 planes)
            uint32_t bfr[2][2][4];
            #pragma unroll
            for (int p = 0; p < 2; ++p)
                #pragma unroll
                for (int ng = 0; ng < 2; ++ng) {
                    int nrow = wn * 32 + ng * 16 + l15;
                    uint32_t off = (uint32_t)(nrow * 128 + ks * 32) + khalf;
                    ldsm4(bfr[p][ng], st + OFF_BH + p * PLANE_B_SZ + sw128(off));
                }
            #pragma unroll
            for (int mf = 0; mf < 4; ++mf) {
                uint32_t af[2][4];
                int arow = wm * 64 + mf * 16 + l15;
                uint32_t off = (uint32_t)(arow * 128 + ks * 32) + khalf;
                ldsm4(af[0], st + sw128(off));
                ldsm4(af[1], st + PLANE_A + sw128(off));
                #pragma unroll
                for (int nf = 0; nf < 4; ++nf) {
                    int ng = nf >> 1, h = nf & 1;
                    mma_bf16(acc[mf][nf], af[0], bfr[0][ng][h], bfr[0][ng][2 + h]);
                    mma_bf16(acc[mf][nf], af[0], bfr[1][ng][h], bfr[1][ng][2 + h]);
                    mma_bf16(acc[mf][nf], af[1], bfr[0][ng][h], bfr[0][ng][2 + h]);
                }
            }
        }
    }
    __syncthreads();

    // ---------------- histogram epilogue ----------------
    // 16 warp-private hists of 32 cols x 20 bins = 40KB (reuse stage smem)
    float* hall = (float*)smem;
    for (int i = tid; i < 16 * 32 * BINS; i += NTHREADS) hall[i] = 0.0f;
    __syncthreads();

    float* hw = hall + wid * (32 * BINS);
    const int q = lane & 3;
    #pragma unroll
    for (int nf = 0; nf < 4; ++nf) {
        #pragma unroll
        for (int half = 0; half < 2; ++half) {
            int lc = nf * 8 + 2 * q + half;      // col within warp's 32
            int c  = wn * 32 + lc;
            float mn = mnS[c], mx = mxS[c], sc = scS[c];
            #pragma unroll
            for (int mf = 0; mf < 4; ++mf)
                #pragma unroll
                for (int rp = 0; rp < 2; ++rp) {
                    float p = acc[mf][nf][2 * rp + half];
                    if (p >= mn && p <= mx) {
                        int b = min((int)((p - mn) * sc), BINS - 1);
                        atomicAdd(&hw[lc * BINS + b], 1.0f);
                    }
                }
        }
    }
    __syncthreads();

    // merge the 4 warp copies per column group -> global atomics
    for (int i = tid; i < BN * BINS; i += NTHREADS) {
        int c = i / BINS, b = i - c * BINS;
        int cwn = c >> 5, lc = c & 31;
        float s = 0.0f;
        #pragma unroll
        for (int k = 0; k < 4; ++k)
            s += hall[(cwn * 4 + k) * (32 * BINS) + lc * BINS + b];
        if (s != 0.0f)
            atomicAdd(&g_hist[(size_t)n0t * BINS + i], s);
    }
}

// ---------------- normalize ----------------
__global__ void normalize_kernel(float* __restrict__ out)
{
    int row  = blockIdx.x * 4 + (threadIdx.x >> 5);
    int lane = threadIdx.x & 31;
    if (row >= D_TOT) return;
    float v = (lane < BINS) ? g_hist[row * BINS + lane] : 0.0f;
    float s = v * v;
    #pragma unroll
    for (int o = 16; o; o >>= 1) s += __shfl_xor_sync(0xFFFFFFFFu, s, o);
    float denom = fmaxf(sqrtf(s), 1e-12f);
    if (lane < BINS) out[row * BINS + lane] = v / denom;
}

extern "C" void kernel_launch(void* const* d_in, const int* in_sizes, int n_in,
                              void* d_out, int out_size)
{
    const float* x    = (const float*)d_in[0];
    const float* W    = (const float*)d_in[1];
    const float* mins = (const float*)d_in[2];
    const float* maxs = (const float*)d_in[3];
    float* out = (float*)d_out;

    static int attr_set = 0;
    if (!attr_set) {
        cudaFuncSetAttribute(gemm_hist_kernel,
                             cudaFuncAttributeMaxDynamicSharedMemorySize, SMEM_TOTAL);
        attr_set = 1;
    }

    __nv_bfloat16 *xhi, *xlo, *whi, *wlo;
    cudaGetSymbolAddress((void**)&xhi, g_xhi);
    cudaGetSymbolAddress((void**)&xlo, g_xlo);
    cudaGetSymbolAddress((void**)&whi, g_whi);
    cudaGetSymbolAddress((void**)&wlo, g_wlo);

    int nx4 = S_ROWS * K_DIM / 4;
    int nw4 = D_TOT * K_DIM / 4;
    split_kernel<<<(nx4 + 255) / 256, 256>>>((const float4*)x, (uint2*)xhi, (uint2*)xlo, nx4);
    split_kernel<<<(nw4 + 255) / 256, 256>>>((const float4*)W, (uint2*)whi, (uint2*)wlo, nw4);
    zero_hist_kernel<<<(D_TOT * BINS + 255) / 256, 256>>>();

    dim3 grid(D_TOT / BN, S_ROWS / BM);   // (50, 64)
    gemm_hist_kernel<<<grid, NTHREADS, SMEM_TOTAL>>>(mins, maxs);

    normalize_kernel<<<(D_TOT + 3) / 4, 128>>>(out);
}